// round 14
// baseline (speedup 1.0000x reference)
#include <cuda_runtime.h>
#include <math.h>
#include <stdint.h>

// ---------------- problem constants ----------------
#define S_LEN   32
#define T_LEN   32
#define BATCH   512
#define HID     1024
#define EMB     256
#define ADIM    1024
#define VSRC    64
#define VTGT    70
#define START_TOK 1
#define G3H     (3*HID)
#define NCOMB   4096          // [hW (1024) | gh_r | gh_z | gh_n]

// ---------------- scratch (static __device__ — no allocation) ----------------
__device__ float g_Menc[VSRC*G3H];
__device__ float g_Mtgt[VTGT*G3H];
__device__ float g_h[BATCH*HID];
__device__ float g_encops[S_LEN*BATCH*HID];
__device__ float g_encpart[S_LEN*BATCH*ADIM];
__device__ float g_gh[BATCH*G3H];
__device__ float g_gi[BATCH*G3H];
__device__ float g_hWgh[BATCH*NCOMB];
__device__ float g_ctx[BATCH*HID];
__device__ int   g_x[BATCH];
// weights, tf32-rounded, stored [N][K]
__device__ float g_Whe[G3H*HID];      // W_hh_enc (already (3H,H))
__device__ float g_Wid[G3H*HID];      // W_ih_dec[:, :H]
__device__ float g_Wcomb[NCOMB*HID];  // rows: [W_attn[:H]^T (1024) | W_hh_dec (3072)]
__device__ float g_Wap[ADIM*HID];     // W_attn[H:]^T
__device__ float g_bcomb[NCOMB];
__device__ float g_WoutT[VTGT*HID];   // W_out^T (fp32, coalesced logits)

// ---------------- tf32 helpers ----------------
__device__ __forceinline__ unsigned f2tf(float f) {
    unsigned u; asm("cvt.rna.tf32.f32 %0, %1;" : "=r"(u) : "f"(f)); return u;
}
__device__ __forceinline__ float f2tf_f(float f) { return __uint_as_float(f2tf(f)); }

__device__ __forceinline__ void mma8(float* c, const uint4 a, unsigned b0, unsigned b1) {
    asm volatile("mma.sync.aligned.m16n8k8.row.col.f32.tf32.tf32.f32 "
        "{%0,%1,%2,%3}, {%4,%5,%6,%7}, {%8,%9}, {%0,%1,%2,%3};"
        : "+f"(c[0]), "+f"(c[1]), "+f"(c[2]), "+f"(c[3])
        : "r"(a.x), "r"(a.y), "r"(a.z), "r"(a.w), "r"(b0), "r"(b1));
}

// ---------------- fragment-staged tf32 GEMM: C[M,N] = A[M,K] @ Bw[N,K]^T (+bias) ----
// Tile 128x128x32, 256 threads, warp grid 2(m) x 4(n), warp tile 64x32.
// SMEM holds operands in mma-fragment order so inner loop uses LDS.128 only.
//   Fragment float index = block*128 + lane*4 + f, lane = g*4 + t (t = k in quad).
//   A: f = {A[g][t4], A[g+8][t4], A[g][t4+4], A[g+8][t4+4]} per 16-row tile.
//   B: f = {B(t4,n), B(t4+4,n), B(t4,n+8), B(t4+4,n+8)}, n = ntp*16 + g.
// M, N multiples of 128; K multiple of 32.
__global__ __launch_bounds__(256)
void gemm_tf32(const float* __restrict__ A, int lda,
               const float* __restrict__ Bw, int ldb,
               float* __restrict__ C, int ldc,
               int K, const float* __restrict__ bias)
{
    __shared__ float sA[4096];     // 16 KB
    __shared__ float sB[4096];     // 16 KB
    const int tid = threadIdx.x, wid = tid >> 5, lane = tid & 31;
    const int wm = wid & 1, wn = wid >> 1;       // warp origin (wm*64, wn*32)
    const int m0 = blockIdx.y * 128, n0 = blockIdx.x * 128;

    // staging coords: this thread owns source row sm (both A-m and B-n), quads q0..q0+3
    const int sm = tid >> 1;          // 0..127
    const int q0 = (tid & 1) * 4;     // k-quad base: 0 or 4   (k = q*4)
    const float* arow = A  + (size_t)(m0 + sm) * lda;
    const float* brow = Bw + (size_t)(n0 + sm) * ldb;

    // precomputed scatter bases for staging
    const int a_mt = sm >> 4, a_r = sm & 15;
    const int a_base = a_r >> 3, a_g = a_r & 7;
    const int b_ntp = sm >> 4, b_r = sm & 15;
    const int b_sub = b_r >> 3, b_g = b_r & 7;

    float acc[4][4][4];
#pragma unroll
    for (int i = 0; i < 4; ++i)
#pragma unroll
        for (int j = 0; j < 4; ++j)
#pragma unroll
            for (int q = 0; q < 4; ++q) acc[i][j][q] = 0.f;

    const int nch = K / 32;
    float4 pa[4], pb[4];
#pragma unroll
    for (int i = 0; i < 4; ++i) {
        pa[i] = *(const float4*)(arow + (q0 + i) * 4);
        pb[i] = *(const float4*)(brow + (q0 + i) * 4);
    }

    for (int c = 0; c < nch; ++c) {
        // ---- stage prefetched chunk into fragment-order smem ----
#pragma unroll
        for (int i = 0; i < 4; ++i) {
            const int q = q0 + i;                 // k = q*4 .. q*4+3
            const int ks = q >> 1, up = q & 1;
            {   // A: f-index = a_base + 2*up; element t lands at +4*t (lane = a_g*4 + t)
                const int slot = ((ks * 8 + a_mt) * 32 + a_g * 4) * 4 + a_base + 2 * up;
                const float* v = (const float*)&pa[i];
#pragma unroll
                for (int t = 0; t < 4; ++t)
                    sA[slot + 4 * t] = f2tf_f(v[t]);
            }
            {   // B: f-index = up + 2*b_sub (already tf32-rounded)
                const int slot = ((ks * 8 + b_ntp) * 32 + b_g * 4) * 4 + up + 2 * b_sub;
                const float* v = (const float*)&pb[i];
#pragma unroll
                for (int t = 0; t < 4; ++t)
                    sB[slot + 4 * t] = v[t];
            }
        }
        __syncthreads();

        // ---- prefetch next chunk (overlaps with compute below) ----
        if (c + 1 < nch) {
            const float* an = arow + (c + 1) * 32;
            const float* bn = brow + (c + 1) * 32;
#pragma unroll
            for (int i = 0; i < 4; ++i) {
                pa[i] = *(const float4*)(an + (q0 + i) * 4);
                pb[i] = *(const float4*)(bn + (q0 + i) * 4);
            }
        }

        // ---- compute: 4 k-slices, all via LDS.128 ----
#pragma unroll
        for (int ks = 0; ks < 4; ++ks) {
            uint4 af[4], bf[2];
#pragma unroll
            for (int mt = 0; mt < 4; ++mt)
                af[mt] = *(const uint4*)&sA[((ks * 8 + wm * 4 + mt) * 32 + lane) * 4];
#pragma unroll
            for (int np = 0; np < 2; ++np)
                bf[np] = *(const uint4*)&sB[((ks * 8 + wn * 2 + np) * 32 + lane) * 4];
#pragma unroll
            for (int mt = 0; mt < 4; ++mt)
#pragma unroll
                for (int np = 0; np < 2; ++np) {
                    mma8(acc[mt][np * 2],     af[mt], bf[np].x, bf[np].y);
                    mma8(acc[mt][np * 2 + 1], af[mt], bf[np].z, bf[np].w);
                }
        }
        __syncthreads();
    }

    // ---- epilogue ----
    const int g = lane >> 2, t4 = lane & 3;
#pragma unroll
    for (int mt = 0; mt < 4; ++mt) {
        const int mrow = m0 + wm * 64 + mt * 16 + g;
#pragma unroll
        for (int nt = 0; nt < 4; ++nt) {
            const int n = n0 + wn * 32 + nt * 8 + 2 * t4;
            float b0 = bias ? bias[n] : 0.f;
            float b1 = bias ? bias[n + 1] : 0.f;
            *(float2*)(C + (size_t)mrow * ldc + n) =
                make_float2(acc[mt][nt][0] + b0, acc[mt][nt][1] + b1);
            *(float2*)(C + (size_t)(mrow + 8) * ldc + n) =
                make_float2(acc[mt][nt][2] + b0, acc[mt][nt][3] + b1);
        }
    }
}

// ---------------- weight prep (tf32 round; layout [N][K]) ----------------
__global__ void prep_whe(const float* __restrict__ W) {       // (3H,H) direct
    int idx = blockIdx.x * 256 + threadIdx.x;
    if (idx < G3H * HID) g_Whe[idx] = f2tf_f(W[idx]);
}
__global__ void prep_wid(const float* __restrict__ W) {       // W_ih_dec[:, :H]
    int idx = blockIdx.x * 256 + threadIdx.x;
    if (idx >= G3H * HID) return;
    int n = idx / HID, k = idx % HID;
    g_Wid[idx] = f2tf_f(W[(size_t)n * (HID + EMB) + k]);
}
__global__ void prep_wcomb(const float* __restrict__ Wattn, const float* __restrict__ Whd,
                           const float* __restrict__ bhh) {
    int idx = blockIdx.x * 256 + threadIdx.x;
    if (idx >= NCOMB * HID) return;
    int n = idx / HID, k = idx % HID;
    float v = (n < ADIM) ? Wattn[(size_t)k * ADIM + n]       // W_attn[:H]^T
                         : Whd[(size_t)(n - ADIM) * HID + k];
    g_Wcomb[idx] = f2tf_f(v);
    if (idx < NCOMB) g_bcomb[idx] = (idx < ADIM) ? 0.f : bhh[idx - ADIM];
}
__global__ void prep_wap(const float* __restrict__ Wattn) {   // W_attn[H:]^T
    int idx = blockIdx.x * 256 + threadIdx.x;
    if (idx >= ADIM * HID) return;
    int n = idx / HID, k = idx % HID;
    g_Wap[idx] = f2tf_f(Wattn[(size_t)(HID + k) * ADIM + n]);
}
__global__ void prep_woutT(const float* __restrict__ Wout) {  // (H,VT) -> (VT,H)
    int idx = blockIdx.x * 256 + threadIdx.x;
    if (idx >= VTGT * HID) return;
    int v = idx / HID, k = idx % HID;
    g_WoutT[idx] = Wout[(size_t)k * VTGT + v];
}

// ---------------- embedding precompute (biases folded, fp32 exact) ----------------
__global__ void emb_gemm(const float* __restrict__ emb, const float* __restrict__ W,
                         const float* __restrict__ bias, float* __restrict__ out,
                         int rows, int ldw, int off)
{
    int idx = blockIdx.x * blockDim.x + threadIdx.x;
    if (idx >= rows * G3H) return;
    int i = idx / G3H, gg = idx % G3H;
    const float* er = emb + (size_t)i * EMB;
    const float* wr = W + (size_t)gg * ldw + off;
    float acc = bias[gg];
#pragma unroll 8
    for (int e = 0; e < EMB; ++e) acc = fmaf(er[e], wr[e], acc);
    out[idx] = acc;
}

__device__ __forceinline__ float sigm(float x) { return 1.f / (1.f + expf(-x)); }

// ---------------- encoder gates ----------------
__global__ void enc_gates(const int* __restrict__ src, int s)
{
    int idx = blockIdx.x * 256 + threadIdx.x;
    int b = idx >> 10, j = idx & 1023;
    int id = src[s * BATCH + b];
    const float* mi = g_Menc + (size_t)id * G3H;
    const float* gh = g_gh   + (size_t)b  * G3H;
    float r = sigm(mi[j]          + gh[j]);
    float z = sigm(mi[HID + j]    + gh[HID + j]);
    float n = tanhf(mi[2*HID + j] + r * gh[2*HID + j]);
    float hold = g_h[idx];
    float hn = (1.f - z) * n + z * hold;
    g_h[idx] = hn;
    g_encops[(size_t)s * BATCH * HID + idx] = hn;
}

// ---------------- fused attention: scores -> softmax -> ctx + attn out ----------
__global__ __launch_bounds__(256)
void attn_fused(const float* __restrict__ v_attn, float* __restrict__ attn_row)
{
    int b = blockIdx.x, tid = threadIdx.x;
    int w = tid >> 5, lane = tid & 31;
    __shared__ float sc[S_LEN];
    __shared__ float al[S_LEN];
    const float* hw = g_hWgh + (size_t)b * NCOMB;
#pragma unroll
    for (int i = 0; i < 4; ++i) {
        int s = w + 8 * i;
        const float* ep = g_encpart + ((size_t)s * BATCH + b) * ADIM;
        float p = 0.f;
#pragma unroll 4
        for (int a = lane; a < ADIM; a += 32)
            p = fmaf(v_attn[a], tanhf(ep[a] + hw[a]), p);
#pragma unroll
        for (int o = 16; o; o >>= 1) p += __shfl_xor_sync(0xffffffffu, p, o);
        if (lane == 0) sc[s] = p;
    }
    __syncthreads();
    if (tid < 32) {
        float x = sc[tid];
        float m = x;
#pragma unroll
        for (int o = 16; o; o >>= 1) m = fmaxf(m, __shfl_xor_sync(0xffffffffu, m, o));
        float e = expf(x - m);
        float smv = e;
#pragma unroll
        for (int o = 16; o; o >>= 1) smv += __shfl_xor_sync(0xffffffffu, smv, o);
        float a = e / smv;
        al[tid] = a;
        attn_row[(size_t)b * S_LEN + tid] = a;
    }
    __syncthreads();
    for (int h = tid; h < HID; h += 256) {
        float acc = 0.f;
#pragma unroll
        for (int s2 = 0; s2 < S_LEN; ++s2)
            acc = fmaf(al[s2], g_encops[((size_t)s2 * BATCH + b) * HID + h], acc);
        g_ctx[(size_t)b * HID + h] = acc;
    }
}

// ---------------- fused decoder gates + output projection + next token ----------
__global__ __launch_bounds__(256)
void dec_out(const float* __restrict__ b_out, const int* __restrict__ tgt,
             const int* __restrict__ tfp, float* __restrict__ out_t, int t)
{
    int b = blockIdx.x, tid = threadIdx.x;
    __shared__ float hs[HID];
    __shared__ float vals[VTGT];
    int id = g_x[b];
    const float* mi = g_Mtgt + (size_t)id * G3H;
    const float* gi = g_gi   + (size_t)b  * G3H;
    const float* gh = g_hWgh + (size_t)b  * NCOMB + ADIM;
#pragma unroll
    for (int u = 0; u < 4; ++u) {
        int j = tid + 256 * u;
        float r = sigm(mi[j]          + gi[j]          + gh[j]);
        float z = sigm(mi[HID + j]    + gi[HID + j]    + gh[HID + j]);
        float n = tanhf(mi[2*HID + j] + gi[2*HID + j]  + r * gh[2*HID + j]);
        float hold = g_h[(size_t)b * HID + j];
        float hn = (1.f - z) * n + z * hold;
        g_h[(size_t)b * HID + j] = hn;
        hs[j] = hn;
    }
    __syncthreads();
    int w = tid >> 5, lane = tid & 31;
    for (int v = w; v < VTGT; v += 8) {
        const float* wr = g_WoutT + (size_t)v * HID;
        float acc = 0.f;
#pragma unroll 4
        for (int k = lane; k < HID; k += 32) acc = fmaf(hs[k], wr[k], acc);
#pragma unroll
        for (int o = 16; o; o >>= 1) acc += __shfl_xor_sync(0xffffffffu, acc, o);
        if (lane == 0) {
            float o = acc + b_out[v];
            out_t[(size_t)b * VTGT + v] = o;
            vals[v] = o;
        }
    }
    __syncthreads();
    if (tid == 0) {
        int nx;
        if (tfp[0]) nx = tgt[t * BATCH + b];
        else {
            float bm = vals[0]; nx = 0;
            for (int v = 1; v < VTGT; ++v) if (vals[v] > bm) { bm = vals[v]; nx = v; }
        }
        g_x[b] = nx;
    }
}

// ---------------- small init kernels ----------------
__global__ void zero_h() { g_h[blockIdx.x * 256 + threadIdx.x] = 0.f; }
__global__ void init_x(const int* __restrict__ tgt)
{
    int b = blockIdx.x * 64 + threadIdx.x;
    if (b < BATCH) g_x[b] = tgt[b];
}
__global__ void row0(float* __restrict__ out0)
{
    int idx = blockIdx.x * 256 + threadIdx.x;
    if (idx < BATCH * VTGT) out0[idx] = ((idx % VTGT) == START_TOK) ? 1.f : 0.f;
}

// ---------------- host launcher (graph-capturable: kernels only) ----------------
extern "C" void kernel_launch(void* const* d_in, const int* in_sizes, int n_in,
                              void* d_out, int out_size)
{
    const int*   src      = (const int*)  d_in[0];
    const int*   tgt      = (const int*)  d_in[1];
    const int*   tf       = (const int*)  d_in[2];
    const float* emb_src  = (const float*)d_in[3];
    const float* W_ih_enc = (const float*)d_in[4];
    const float* W_hh_enc = (const float*)d_in[5];
    const float* b_ih_enc = (const float*)d_in[6];
    const float* b_hh_enc = (const float*)d_in[7];
    const float* emb_tgt  = (const float*)d_in[8];
    const float* W_attn   = (const float*)d_in[9];
    const float* b_attn   = (const float*)d_in[10];
    const float* v_attn   = (const float*)d_in[11];
    const float* W_ih_dec = (const float*)d_in[12];
    const float* W_hh_dec = (const float*)d_in[13];
    const float* b_ih_dec = (const float*)d_in[14];
    const float* b_hh_dec = (const float*)d_in[15];
    const float* W_out    = (const float*)d_in[16];
    const float* b_out    = (const float*)d_in[17];

    float* outp  = (float*)d_out;
    float* attnp = outp + (size_t)T_LEN * BATCH * VTGT;

    void *pMenc, *pMtgt, *ph, *pencops, *pencpart, *pgh, *pgi, *phWgh, *pctx;
    void *pWhe, *pWid, *pWcomb, *pWap, *pbcomb;
    cudaGetSymbolAddress(&pMenc,    g_Menc);
    cudaGetSymbolAddress(&pMtgt,    g_Mtgt);
    cudaGetSymbolAddress(&ph,       g_h);
    cudaGetSymbolAddress(&pencops,  g_encops);
    cudaGetSymbolAddress(&pencpart, g_encpart);
    cudaGetSymbolAddress(&pgh,      g_gh);
    cudaGetSymbolAddress(&pgi,      g_gi);
    cudaGetSymbolAddress(&phWgh,    g_hWgh);
    cudaGetSymbolAddress(&pctx,     g_ctx);
    cudaGetSymbolAddress(&pWhe,     g_Whe);
    cudaGetSymbolAddress(&pWid,     g_Wid);
    cudaGetSymbolAddress(&pWcomb,   g_Wcomb);
    cudaGetSymbolAddress(&pWap,     g_Wap);
    cudaGetSymbolAddress(&pbcomb,   g_bcomb);

    // ---- weight prep ----
    prep_whe  <<<(G3H  * HID  + 255) / 256, 256>>>(W_hh_enc);
    prep_wid  <<<(G3H  * HID  + 255) / 256, 256>>>(W_ih_dec);
    prep_wcomb<<<(NCOMB* HID  + 255) / 256, 256>>>(W_attn, W_hh_dec, b_hh_dec);
    prep_wap  <<<(ADIM * HID  + 255) / 256, 256>>>(W_attn);
    prep_woutT<<<(VTGT * HID  + 255) / 256, 256>>>(W_out);

    // ---- embedding precompute ----
    emb_gemm<<<(VSRC * G3H + 255) / 256, 256>>>(emb_src, W_ih_enc, b_ih_enc,
                                                (float*)pMenc, VSRC, EMB, 0);
    emb_gemm<<<(VTGT * G3H + 255) / 256, 256>>>(emb_tgt, W_ih_dec, b_ih_dec,
                                                (float*)pMtgt, VTGT, HID + EMB, HID);
    zero_h<<<BATCH * HID / 256, 256>>>();
    init_x<<<(BATCH + 63) / 64, 64>>>(tgt);
    row0<<<(BATCH * VTGT + 255) / 256, 256>>>(outp);

    // ---- encoder: 32 sequential GRU steps ----
    dim3 gEnc(G3H / 128, BATCH / 128);   // (24, 4)
    for (int s = 0; s < S_LEN; ++s) {
        gemm_tf32<<<gEnc, 256>>>((const float*)ph, HID, (const float*)pWhe, HID,
                                 (float*)pgh, G3H, HID, b_hh_enc);
        enc_gates<<<BATCH * HID / 256, 256>>>(src, s);
    }

    // ---- attention precompute: enc_part = enc_ops @ W_attn[H:] + b_attn ----
    dim3 gEP(ADIM / 128, (S_LEN * BATCH) / 128);   // (8, 128)
    gemm_tf32<<<gEP, 256>>>((const float*)pencops, HID, (const float*)pWap, HID,
                            (float*)pencpart, ADIM, HID, b_attn);

    // ---- decoder: 31 sequential steps ----
    dim3 gComb(NCOMB / 128, BATCH / 128);  // (32, 4)
    dim3 gGi(G3H / 128, BATCH / 128);      // (24, 4)
    for (int t = 1; t < T_LEN; ++t) {
        gemm_tf32<<<gComb, 256>>>((const float*)ph, HID, (const float*)pWcomb, HID,
                                  (float*)phWgh, NCOMB, HID, (const float*)pbcomb);
        attn_fused<<<BATCH, 256>>>(v_attn, attnp + (size_t)(t - 1) * BATCH * S_LEN);
        gemm_tf32<<<gGi, 256>>>((const float*)pctx, HID, (const float*)pWid, HID,
                                (float*)pgi, G3H, HID, nullptr);
        dec_out<<<BATCH, 256>>>(b_out, tgt, tf, outp + (size_t)t * BATCH * VTGT, t);
    }
}